// round 12
// baseline (speedup 1.0000x reference)
#include <cuda_runtime.h>
#include <float.h>
#include <math.h>

// Problem constants
#define Bc  2
#define Sc  2048
#define Dc  1024
#define Hc  16
#define DKc 64
#define KSEL 32

// Scratch (static device globals — no allocation)
__device__ float g_q[Bc*Hc*Sc*DKc];    // [b][h][s][dk]
__device__ float g_k[Bc*Hc*Sc*DKc];
__device__ float g_v[Bc*Hc*Sc*DKc];
__device__ float g_ctx[Bc*Sc*Dc];      // merged-head [b][s][h*DK+dk]

// ---------------------------------------------------------------------------
// GEMM: Y[m, j] = sum_k X[m,k] * W[j,k] + bias[j]
// Accumulation order replicates XLA:CPU -> Eigen(master) MT gebp on aarch64:
//   ARM64 default l1 = 32KB  =>  k_cache = (32768-192)/64 = 509 -> kc = 504
//   k-panels {504, 504, 16}; single ascending IEEE-fma chain per panel;
//   panel sums added to the running result in ascending order; bias last.
// Panel boundaries at k = 504, 1008, 1024:
//   tile 31 local-k 8, tile 62 end, tile 63 end.
// MODE 0: flat output Y[m*Dc + j]
// MODE 1: head-split output Y[((b*H + h)*S + s)*DK + dk]
// ---------------------------------------------------------------------------
template<int MODE>
__global__ void __launch_bounds__(256)
gemm_bias_kernel(const float* __restrict__ X, const float* __restrict__ W,
                 const float* __restrict__ bias, float* __restrict__ Y)
{
    __shared__ float Xs[16][64];
    __shared__ float Ws[16][64];

    const int tid  = threadIdx.x;
    const int m0   = blockIdx.y * 64;
    const int n0   = blockIdx.x * 64;
    const int lrow = tid >> 2;          // 0..63
    const int lk   = (tid & 3) * 4;     // 0,4,8,12
    const int tx   = tid & 15;
    const int ty   = tid >> 4;

    float acc[4][4];                    // running sum of completed panels
    float pan[4][4];                    // current panel chain
#pragma unroll
    for (int i = 0; i < 4; ++i)
#pragma unroll
        for (int j = 0; j < 4; ++j) { acc[i][j] = 0.f; pan[i][j] = 0.f; }

    const float* Xp = X + (m0 + lrow) * Dc + lk;
    const float* Wp = W + (n0 + lrow) * Dc + lk;

    for (int tile = 0; tile < 64; ++tile) {
        const int k0 = tile * 16;
        float4 xv = *(const float4*)(Xp + k0);
        float4 wv = *(const float4*)(Wp + k0);
        Xs[lk + 0][lrow] = xv.x; Xs[lk + 1][lrow] = xv.y;
        Xs[lk + 2][lrow] = xv.z; Xs[lk + 3][lrow] = xv.w;
        Ws[lk + 0][lrow] = wv.x; Ws[lk + 1][lrow] = wv.y;
        Ws[lk + 2][lrow] = wv.z; Ws[lk + 3][lrow] = wv.w;
        __syncthreads();

#pragma unroll
        for (int half = 0; half < 2; ++half) {
#pragma unroll
            for (int kq = 0; kq < 8; ++kq) {
                const int k = half * 8 + kq;
                float4 a = *(const float4*)&Xs[k][ty * 4];
                float4 b = *(const float4*)&Ws[k][tx * 4];
                pan[0][0] = fmaf(a.x, b.x, pan[0][0]);
                pan[0][1] = fmaf(a.x, b.y, pan[0][1]);
                pan[0][2] = fmaf(a.x, b.z, pan[0][2]);
                pan[0][3] = fmaf(a.x, b.w, pan[0][3]);
                pan[1][0] = fmaf(a.y, b.x, pan[1][0]);
                pan[1][1] = fmaf(a.y, b.y, pan[1][1]);
                pan[1][2] = fmaf(a.y, b.z, pan[1][2]);
                pan[1][3] = fmaf(a.y, b.w, pan[1][3]);
                pan[2][0] = fmaf(a.z, b.x, pan[2][0]);
                pan[2][1] = fmaf(a.z, b.y, pan[2][1]);
                pan[2][2] = fmaf(a.z, b.z, pan[2][2]);
                pan[2][3] = fmaf(a.z, b.w, pan[2][3]);
                pan[3][0] = fmaf(a.w, b.x, pan[3][0]);
                pan[3][1] = fmaf(a.w, b.y, pan[3][1]);
                pan[3][2] = fmaf(a.w, b.z, pan[3][2]);
                pan[3][3] = fmaf(a.w, b.w, pan[3][3]);
            }
            // Mid-tile panel boundary: k=504 (tile 31, after local k 0..7)
            if (half == 0 && tile == 31) {
#pragma unroll
                for (int i = 0; i < 4; ++i)
#pragma unroll
                    for (int j = 0; j < 4; ++j) {
                        acc[i][j] += pan[i][j];
                        pan[i][j] = 0.f;
                    }
            }
        }
        // End-of-tile panel boundaries: k=1008 (tile 62), k=1024 (tile 63)
        if (tile == 62 || tile == 63) {
#pragma unroll
            for (int i = 0; i < 4; ++i)
#pragma unroll
                for (int j = 0; j < 4; ++j) {
                    acc[i][j] += pan[i][j];
                    pan[i][j] = 0.f;
                }
        }
        __syncthreads();
    }

#pragma unroll
    for (int i = 0; i < 4; ++i) {
        const int m = m0 + ty * 4 + i;
#pragma unroll
        for (int j = 0; j < 4; ++j) {
            const int c = n0 + tx * 4 + j;
            const float v = acc[i][j] + bias[c];
            if (MODE == 0) {
                Y[m * Dc + c] = v;
            } else {
                const int b  = m >> 11;            // m / S
                const int s  = m & (Sc - 1);
                const int h  = c >> 6;             // c / DK
                const int dk = c & 63;
                Y[(((b * Hc + h) * Sc) + s) * DKc + dk] = v;
            }
        }
    }
}

// ---------------------------------------------------------------------------
// Fused attention: per block = 16 query rows of one (b,h).
//   scores: SINGLE sequential ascending fp32 fma chain per score
//           (k=64 < kc => single panel => matches Eigen gebp)
//   top-32: iterative warp argmax, lowest-index tie-break (== lax.top_k)
//   softmax: denominator = strictly ascending sequential sum
//   ctx = sum_sel p * V[idx], ascending
// 512 threads, ~136 KB dynamic smem.
// ---------------------------------------------------------------------------
#define TQ 16
#define SSTRIDE 2049   // odd stride

__global__ void __launch_bounds__(512)
attn_kernel(const int* __restrict__ mask, const int* __restrict__ topk_p)
{
    extern __shared__ float sm[];
    float* qs   = sm;                        // TQ*64
    float* sc   = sm + TQ * 64;              // TQ*SSTRIDE
    float* selv = sc + TQ * SSTRIDE;         // TQ*32
    float* sele = selv + TQ * 32;            // TQ*32 (exp values)
    int*   seli = (int*)(sele + TQ * 32);    // TQ*32

    const int tid = threadIdx.x;
    const int bh  = blockIdx.y;
    const int b   = bh >> 4;
    const int h   = bh & 15;
    const int q0  = blockIdx.x * TQ;

    const float* Qb = g_q + ((size_t)bh * Sc + q0) * DKc;
    const float* Kb = g_k + (size_t)bh * Sc * DKc;
    const float* Vb = g_v + (size_t)bh * Sc * DKc;

    // load Q tile into smem (contiguous)
    for (int i = tid; i < TQ * DKc; i += 512) qs[i] = Qb[i];
    __syncthreads();

    // ---- scores ----
    {
        const int r   = tid & 15;            // query row
        const int grp = tid >> 4;            // 0..31, each group -> 64 keys
        const int*  mrow = mask + ((size_t)b * Sc + (q0 + r)) * Sc;
        float* srow = sc + r * SSTRIDE;

        // preload this thread's q row into registers (16 float4)
        float4 qv[16];
#pragma unroll
        for (int d = 0; d < 16; ++d)
            qv[d] = *(const float4*)(qs + r * DKc + d * 4);

        for (int jj = 0; jj < 64; jj += 2) {
            const int j = grp * 64 + jj;
            const float4* k0p = (const float4*)(Kb + (size_t)j * DKc);
            const float4* k1p = (const float4*)(Kb + (size_t)(j + 1) * DKc);
            // Two independent scores, each a SINGLE ascending fma chain.
            float s0 = 0.f, s1 = 0.f;
#pragma unroll
            for (int d = 0; d < 16; ++d) {
                float4 k0 = k0p[d];
                float4 k1 = k1p[d];
                s0 = fmaf(qv[d].x, k0.x, s0);
                s0 = fmaf(qv[d].y, k0.y, s0);
                s0 = fmaf(qv[d].z, k0.z, s0);
                s0 = fmaf(qv[d].w, k0.w, s0);
                s1 = fmaf(qv[d].x, k1.x, s1);
                s1 = fmaf(qv[d].y, k1.y, s1);
                s1 = fmaf(qv[d].z, k1.z, s1);
                s1 = fmaf(qv[d].w, k1.w, s1);
            }
            s0 *= 0.125f;                    // /sqrt(64): exact
            s1 *= 0.125f;
            if (mrow[j]     == 0) s0 = -1e9f;
            if (mrow[j + 1] == 0) s1 = -1e9f;
            srow[j]     = s0;
            srow[j + 1] = s1;
        }
    }
    __syncthreads();

    int kk = *topk_p;
    if (kk > KSEL) kk = KSEL;

    // ---- top-k: warp w owns query row w ----
    const int w    = tid >> 5;
    const int lane = tid & 31;
    float* scr = sc + w * SSTRIDE;

    for (int sel = 0; sel < kk; ++sel) {
        float bv = -FLT_MAX;
        int   bi = 0x7fffffff;
#pragma unroll 8
        for (int i = 0; i < 64; ++i) {
            const int idx = i * 32 + lane;
            const float v = scr[idx];
            if (v > bv) { bv = v; bi = idx; }
        }
#pragma unroll
        for (int off = 16; off; off >>= 1) {
            const float ov = __shfl_down_sync(0xffffffffu, bv, off);
            const int   oi = __shfl_down_sync(0xffffffffu, bi, off);
            if (ov > bv || (ov == bv && oi < bi)) { bv = ov; bi = oi; }
        }
        bi = __shfl_sync(0xffffffffu, bi, 0);
        bv = __shfl_sync(0xffffffffu, bv, 0);
        if (lane == 0) {
            selv[w * 32 + sel] = bv;
            seli[w * 32 + sel] = bi;
            scr[bi] = -FLT_MAX;              // remove from candidates
        }
        __syncwarp();
    }

    // ---- softmax over selected (sequential ascending denominator) ----
    const float mx = selv[w * 32];           // first pick == row max
    float e = 0.f;
    if (lane < kk) {
        e = expf(selv[w * 32 + lane] - mx);
        sele[w * 32 + lane] = e;
    }
    __syncwarp();
    float ssum = 0.f;
    for (int i = 0; i < kk; ++i)             // strictly ascending, all lanes
        ssum += sele[w * 32 + i];
    const float p = e / ssum;

    // ---- ctx gather (ascending over selections) ----
    int myi = (lane < kk) ? seli[w * 32 + lane] : 0;
    float a0 = 0.f, a1 = 0.f;
    for (int sel = 0; sel < kk; ++sel) {
        const float pp = __shfl_sync(0xffffffffu, p, sel);
        const int   id = __shfl_sync(0xffffffffu, myi, sel);
        const float* vp = Vb + (size_t)id * DKc;
        a0 = fmaf(pp, vp[lane],      a0);
        a1 = fmaf(pp, vp[lane + 32], a1);
    }

    float* outp = g_ctx + ((size_t)(b * Sc + q0 + w)) * Dc + h * DKc;
    outp[lane]      = a0;
    outp[lane + 32] = a1;
}

#define SMEM_ATTN ((TQ*64 + TQ*SSTRIDE + TQ*32 + TQ*32) * 4 + TQ*32 * 4)

// ---------------------------------------------------------------------------
extern "C" void kernel_launch(void* const* d_in, const int* in_sizes, int n_in,
                              void* d_out, int out_size)
{
    const float* query = (const float*)d_in[0];
    const float* key   = (const float*)d_in[1];
    const float* value = (const float*)d_in[2];
    const float* Wq    = (const float*)d_in[3];
    const float* bq    = (const float*)d_in[4];
    const float* Wk    = (const float*)d_in[5];
    const float* bk    = (const float*)d_in[6];
    const float* Wv    = (const float*)d_in[7];
    const float* bv    = (const float*)d_in[8];
    const float* Wo    = (const float*)d_in[9];
    const float* bo    = (const float*)d_in[10];
    const int*   mask  = (const int*)d_in[11];
    const int*   topk  = (const int*)d_in[12];
    float* out = (float*)d_out;

    float *pq, *pk, *pv, *pctx;
    cudaGetSymbolAddress((void**)&pq,   g_q);
    cudaGetSymbolAddress((void**)&pk,   g_k);
    cudaGetSymbolAddress((void**)&pv,   g_v);
    cudaGetSymbolAddress((void**)&pctx, g_ctx);

    cudaFuncSetAttribute(attn_kernel,
                         cudaFuncAttributeMaxDynamicSharedMemorySize, SMEM_ATTN);

    dim3 gg(Dc / 64, (Bc * Sc) / 64);   // (16, 64)

    gemm_bias_kernel<1><<<gg, 256>>>(query, Wq, bq, pq);
    gemm_bias_kernel<1><<<gg, 256>>>(key,   Wk, bk, pk);
    gemm_bias_kernel<1><<<gg, 256>>>(value, Wv, bv, pv);

    attn_kernel<<<dim3(Sc / TQ, Bc * Hc), 512, SMEM_ATTN>>>(mask, topk);

    gemm_bias_kernel<0><<<gg, 256>>>(pctx, Wo, bo, out);
}

// round 13
// speedup vs baseline: 1.8301x; 1.8301x over previous
#include <cuda_runtime.h>
#include <float.h>
#include <math.h>

// Problem constants
#define Bc  2
#define Sc  2048
#define Dc  1024
#define Hc  16
#define DKc 64
#define KSEL 32

// Scratch (static device globals — no allocation)
__device__ float g_q[Bc*Hc*Sc*DKc];    // [b][h][s][dk]
__device__ float g_k[Bc*Hc*Sc*DKc];
__device__ float g_v[Bc*Hc*Sc*DKc];
__device__ float g_ctx[Bc*Sc*Dc];      // merged-head [b][s][h*DK+dk]

// ---------------------------------------------------------------------------
// GEMM v2: Y[m, j] = sum_k X[m,k] * W[j,k] + bias[j]
// 128x128 tile, 8x8 microtile, double-buffered smem, 256 threads.
// PANELS=1: Eigen-MT aarch64 accumulation (kc=504: panels {504,504,16};
//           ascending fma chain per panel, panels added ascending) — BIT-EXACT
//           per element to the R12 passing kernel. Used for Q, K.
// PANELS=0: single ascending chain (fewer regs) — used for V and out-proj,
//           whose ulp-level differences only propagate linearly.
// MODE 0: flat output Y[m*Dc + j]
// MODE 1: head-split output Y[((b*H + h)*S + s)*DK + dk]
// ---------------------------------------------------------------------------
template<int MODE, int PANELS>
__global__ void __launch_bounds__(256, 1)
gemm_v2(const float* __restrict__ X, const float* __restrict__ W,
        const float* __restrict__ bias, float* __restrict__ Y)
{
    __shared__ float Xs[2][16][132];
    __shared__ float Ws[2][16][132];

    const int tid = threadIdx.x;
    const int m0  = blockIdx.y * 128;
    const int n0  = blockIdx.x * 128;
    const int tx  = tid & 15;          // n microtile
    const int ty  = tid >> 4;          // m microtile
    const int lr  = tid >> 2;          // 0..63 loader row
    const int lc  = (tid & 3) << 2;    // 0,4,8,12 loader k col

    const float* Xp0 = X + (size_t)(m0 + lr) * Dc + lc;
    const float* Xp1 = X + (size_t)(m0 + lr + 64) * Dc + lc;
    const float* Wp0 = W + (size_t)(n0 + lr) * Dc + lc;
    const float* Wp1 = W + (size_t)(n0 + lr + 64) * Dc + lc;

    float pan[8][8];
    float acc[8][8];
#pragma unroll
    for (int i = 0; i < 8; ++i)
#pragma unroll
        for (int j = 0; j < 8; ++j) { pan[i][j] = 0.f; if (PANELS) acc[i][j] = 0.f; }

    // preload tile 0
    float4 xa = *(const float4*)Xp0;
    float4 xb = *(const float4*)Xp1;
    float4 wa = *(const float4*)Wp0;
    float4 wb = *(const float4*)Wp1;
    Xs[0][lc+0][lr] = xa.x; Xs[0][lc+1][lr] = xa.y; Xs[0][lc+2][lr] = xa.z; Xs[0][lc+3][lr] = xa.w;
    Xs[0][lc+0][lr+64] = xb.x; Xs[0][lc+1][lr+64] = xb.y; Xs[0][lc+2][lr+64] = xb.z; Xs[0][lc+3][lr+64] = xb.w;
    Ws[0][lc+0][lr] = wa.x; Ws[0][lc+1][lr] = wa.y; Ws[0][lc+2][lr] = wa.z; Ws[0][lc+3][lr] = wa.w;
    Ws[0][lc+0][lr+64] = wb.x; Ws[0][lc+1][lr+64] = wb.y; Ws[0][lc+2][lr+64] = wb.z; Ws[0][lc+3][lr+64] = wb.w;
    __syncthreads();

    int buf = 0;
    for (int tile = 0; tile < 64; ++tile) {
        const bool haveNext = (tile < 63);
        if (haveNext) {
            const int kn = (tile + 1) * 16;
            xa = *(const float4*)(Xp0 + kn);
            xb = *(const float4*)(Xp1 + kn);
            wa = *(const float4*)(Wp0 + kn);
            wb = *(const float4*)(Wp1 + kn);
        }
        const bool midflush = PANELS && (tile == 31);

#pragma unroll
        for (int k = 0; k < 16; ++k) {
            float4 a0 = *(const float4*)&Xs[buf][k][ty * 4];
            float4 a1 = *(const float4*)&Xs[buf][k][64 + ty * 4];
            float4 b0 = *(const float4*)&Ws[buf][k][tx * 4];
            float4 b1 = *(const float4*)&Ws[buf][k][64 + tx * 4];
            float av[8] = {a0.x, a0.y, a0.z, a0.w, a1.x, a1.y, a1.z, a1.w};
            float bv[8] = {b0.x, b0.y, b0.z, b0.w, b1.x, b1.y, b1.z, b1.w};
#pragma unroll
            for (int i = 0; i < 8; ++i)
#pragma unroll
                for (int j = 0; j < 8; ++j)
                    pan[i][j] = fmaf(av[i], bv[j], pan[i][j]);
            if (PANELS && k == 7) {
                if (midflush) {          // k = 504 boundary
#pragma unroll
                    for (int i = 0; i < 8; ++i)
#pragma unroll
                        for (int j = 0; j < 8; ++j) {
                            acc[i][j] += pan[i][j];
                            pan[i][j] = 0.f;
                        }
                }
            }
        }
        if (PANELS && (tile == 62 || tile == 63)) {   // k = 1008, 1024
#pragma unroll
            for (int i = 0; i < 8; ++i)
#pragma unroll
                for (int j = 0; j < 8; ++j) {
                    acc[i][j] += pan[i][j];
                    pan[i][j] = 0.f;
                }
        }
        if (haveNext) {
            const int nb = buf ^ 1;
            Xs[nb][lc+0][lr] = xa.x; Xs[nb][lc+1][lr] = xa.y; Xs[nb][lc+2][lr] = xa.z; Xs[nb][lc+3][lr] = xa.w;
            Xs[nb][lc+0][lr+64] = xb.x; Xs[nb][lc+1][lr+64] = xb.y; Xs[nb][lc+2][lr+64] = xb.z; Xs[nb][lc+3][lr+64] = xb.w;
            Ws[nb][lc+0][lr] = wa.x; Ws[nb][lc+1][lr] = wa.y; Ws[nb][lc+2][lr] = wa.z; Ws[nb][lc+3][lr] = wa.w;
            Ws[nb][lc+0][lr+64] = wb.x; Ws[nb][lc+1][lr+64] = wb.y; Ws[nb][lc+2][lr+64] = wb.z; Ws[nb][lc+3][lr+64] = wb.w;
            __syncthreads();
            buf = nb;
        }
    }

#pragma unroll
    for (int i = 0; i < 8; ++i) {
        const int m = m0 + ((i < 4) ? (ty * 4 + i) : (64 + ty * 4 + i - 4));
#pragma unroll
        for (int j = 0; j < 8; ++j) {
            const int c = n0 + ((j < 4) ? (tx * 4 + j) : (64 + tx * 4 + j - 4));
            const float r = (PANELS ? acc[i][j] : pan[i][j]) + bias[c];
            if (MODE == 0) {
                Y[(size_t)m * Dc + c] = r;
            } else {
                const int bb = m >> 11;            // m / S
                const int s  = m & (Sc - 1);
                const int hh = c >> 6;             // c / DK
                const int dk = c & 63;
                Y[(((size_t)(bb * Hc + hh) * Sc) + s) * DKc + dk] = r;
            }
        }
    }
}

// ---------------------------------------------------------------------------
// Attention v2: per block = 16 query rows of one (b,h).
//   scores: K staged through double-buffered smem; per score a SINGLE
//           ascending fp32 fma chain (bit-identical to R12)
//   top-32: per-lane cached argmax; lane owns 64 scores (idx = j*128+lane*4+t),
//           only the winning lane rescans after removal. Strict >, lowest
//           global index on ties == lax.top_k semantics.
//   softmax: ascending sequential denominator; ctx ascending over selections
// 512 threads, ~170 KB dynamic smem.
// ---------------------------------------------------------------------------
#define TQ 16
#define SST 2052     // row stride (16B aligned, low-conflict)
#define NKT 64       // keys per staged tile

__global__ void __launch_bounds__(512, 1)
attn_v2(const int* __restrict__ mask, const int* __restrict__ topk_p)
{
    extern __shared__ float sm[];
    float* qs   = sm;                          // 16*64
    float* sc   = qs + TQ * 64;                // 16*2052
    float* Ks   = sc + TQ * SST;               // 2 * 64*64
    float* selv = Ks + 2 * NKT * DKc;          // 16*32
    float* sele = selv + TQ * KSEL;            // 16*32
    int*   seli = (int*)(sele + TQ * KSEL);    // 16*32

    const int tid = threadIdx.x;
    const int bh  = blockIdx.y;
    const int b   = bh >> 4;
    const int h   = bh & 15;
    const int q0  = blockIdx.x * TQ;

    const float* Qb = g_q + ((size_t)bh * Sc + q0) * DKc;
    const float* Kb = g_k + (size_t)bh * Sc * DKc;
    const float* Vb = g_v + (size_t)bh * Sc * DKc;

    // load Q tile + K tile 0
    for (int i = tid; i < TQ * DKc; i += 512) qs[i] = Qb[i];
    {
        const float4* src = (const float4*)Kb;
        float4* dst = (float4*)Ks;
        dst[tid]       = src[tid];
        dst[tid + 512] = src[tid + 512];
    }
    __syncthreads();

    // ---- scores ----
    {
        const int r   = tid & 15;              // query row
        const int grp = tid >> 4;              // 0..31 -> 2 keys per tile
        const int* mrow = mask + ((size_t)b * Sc + (q0 + r)) * Sc;
        float* srow = sc + r * SST;

        float4 qv[16];
#pragma unroll
        for (int d = 0; d < 16; ++d)
            qv[d] = *(const float4*)(qs + r * DKc + d * 4);

        int buf = 0;
        for (int kt = 0; kt < Sc / NKT; ++kt) {
            float4 pf0, pf1;
            const bool haveNext = (kt + 1 < Sc / NKT);
            if (haveNext) {
                const float4* src = (const float4*)(Kb + (size_t)(kt + 1) * NKT * DKc);
                pf0 = src[tid];
                pf1 = src[tid + 512];
            }

            const int jl = grp * 2;
            const float4* k0p = (const float4*)(Ks + (size_t)buf * NKT * DKc + (size_t)jl * DKc);
            const float4* k1p = k0p + 16;
            float s0 = 0.f, s1 = 0.f;          // single ascending chains
#pragma unroll
            for (int d = 0; d < 16; ++d) {
                float4 k0 = k0p[d];
                float4 k1 = k1p[d];
                s0 = fmaf(qv[d].x, k0.x, s0);
                s0 = fmaf(qv[d].y, k0.y, s0);
                s0 = fmaf(qv[d].z, k0.z, s0);
                s0 = fmaf(qv[d].w, k0.w, s0);
                s1 = fmaf(qv[d].x, k1.x, s1);
                s1 = fmaf(qv[d].y, k1.y, s1);
                s1 = fmaf(qv[d].z, k1.z, s1);
                s1 = fmaf(qv[d].w, k1.w, s1);
            }
            s0 *= 0.125f;                      // /sqrt(64): exact
            s1 *= 0.125f;
            const int j = kt * NKT + jl;
            const int2 mm = *(const int2*)(mrow + j);
            if (mm.x == 0) s0 = -1e9f;
            if (mm.y == 0) s1 = -1e9f;
            srow[j]     = s0;
            srow[j + 1] = s1;

            if (haveNext) {
                float4* dst = (float4*)(Ks + (size_t)(buf ^ 1) * NKT * DKc);
                dst[tid]       = pf0;
                dst[tid + 512] = pf1;
                __syncthreads();
                buf ^= 1;
            }
        }
    }
    __syncthreads();

    int kk = *topk_p;
    if (kk > KSEL) kk = KSEL;

    // ---- top-k: warp w owns query row w; lane caches its own argmax ----
    const int w    = tid >> 5;
    const int lane = tid & 31;
    float* scr = sc + w * SST;

    float lv; int li;                          // lane's cached (max, idx)
    {
        float nv = -FLT_MAX; int ni = 0x7fffffff;
#pragma unroll
        for (int j = 0; j < 16; ++j) {
            const int base = j * 128 + lane * 4;
            const float4 vv = *(const float4*)&scr[base];
            if (vv.x > nv) { nv = vv.x; ni = base; }
            if (vv.y > nv) { nv = vv.y; ni = base + 1; }
            if (vv.z > nv) { nv = vv.z; ni = base + 2; }
            if (vv.w > nv) { nv = vv.w; ni = base + 3; }
        }
        lv = nv; li = ni;
    }

    for (int sel = 0; sel < kk; ++sel) {
        float bv = lv; int bi = li;
#pragma unroll
        for (int off = 16; off; off >>= 1) {
            const float ov = __shfl_down_sync(0xffffffffu, bv, off);
            const int   oi = __shfl_down_sync(0xffffffffu, bi, off);
            if (ov > bv || (ov == bv && oi < bi)) { bv = ov; bi = oi; }
        }
        bi = __shfl_sync(0xffffffffu, bi, 0);
        bv = __shfl_sync(0xffffffffu, bv, 0);
        if (lane == 0) {
            selv[w * KSEL + sel] = bv;
            seli[w * KSEL + sel] = bi;
        }
        const int owner = (bi >> 2) & 31;      // idx = j*128 + lane*4 + t
        if (lane == owner) {
            scr[bi] = -FLT_MAX;                // remove, then rescan own 64
            float nv = -FLT_MAX; int ni = 0x7fffffff;
#pragma unroll
            for (int j = 0; j < 16; ++j) {
                const int base = j * 128 + lane * 4;
                const float4 vv = *(const float4*)&scr[base];
                if (vv.x > nv) { nv = vv.x; ni = base; }
                if (vv.y > nv) { nv = vv.y; ni = base + 1; }
                if (vv.z > nv) { nv = vv.z; ni = base + 2; }
                if (vv.w > nv) { nv = vv.w; ni = base + 3; }
            }
            lv = nv; li = ni;
        }
        __syncwarp();
    }

    // ---- softmax over selected (sequential ascending denominator) ----
    const float mx = selv[w * KSEL];           // first pick == row max
    float e = 0.f;
    if (lane < kk) {
        e = expf(selv[w * KSEL + lane] - mx);
        sele[w * KSEL + lane] = e;
    }
    __syncwarp();
    float ssum = 0.f;
    for (int i = 0; i < kk; ++i)               // strictly ascending
        ssum += sele[w * KSEL + i];
    const float p = e / ssum;

    // ---- ctx gather (ascending over selections) ----
    const int myi = (lane < kk) ? seli[w * KSEL + lane] : 0;
    float a0 = 0.f, a1 = 0.f;
    for (int sel = 0; sel < kk; ++sel) {
        const float pp = __shfl_sync(0xffffffffu, p, sel);
        const int   id = __shfl_sync(0xffffffffu, myi, sel);
        const float* vp = Vb + (size_t)id * DKc;
        a0 = fmaf(pp, vp[lane],      a0);
        a1 = fmaf(pp, vp[lane + 32], a1);
    }

    float* outp = g_ctx + ((size_t)(b * Sc + q0 + w)) * Dc + h * DKc;
    outp[lane]      = a0;
    outp[lane + 32] = a1;
}

#define SMEM_ATTN ((TQ*64 + TQ*SST + 2*NKT*DKc + TQ*KSEL*2) * 4 + TQ*KSEL * 4)

// ---------------------------------------------------------------------------
extern "C" void kernel_launch(void* const* d_in, const int* in_sizes, int n_in,
                              void* d_out, int out_size)
{
    const float* query = (const float*)d_in[0];
    const float* key   = (const float*)d_in[1];
    const float* value = (const float*)d_in[2];
    const float* Wq    = (const float*)d_in[3];
    const float* bq    = (const float*)d_in[4];
    const float* Wk    = (const float*)d_in[5];
    const float* bk    = (const float*)d_in[6];
    const float* Wv    = (const float*)d_in[7];
    const float* bv    = (const float*)d_in[8];
    const float* Wo    = (const float*)d_in[9];
    const float* bo    = (const float*)d_in[10];
    const int*   mask  = (const int*)d_in[11];
    const int*   topk  = (const int*)d_in[12];
    float* out = (float*)d_out;

    float *pq, *pk, *pv, *pctx;
    cudaGetSymbolAddress((void**)&pq,   g_q);
    cudaGetSymbolAddress((void**)&pk,   g_k);
    cudaGetSymbolAddress((void**)&pv,   g_v);
    cudaGetSymbolAddress((void**)&pctx, g_ctx);

    cudaFuncSetAttribute(attn_v2,
                         cudaFuncAttributeMaxDynamicSharedMemorySize, SMEM_ATTN);

    dim3 gg(Dc / 128, (Bc * Sc) / 128);   // (8, 32)

    // Q, K: bit-exact Eigen panel accumulation
    gemm_v2<1, 1><<<gg, 256>>>(query, Wq, bq, pq);
    gemm_v2<1, 1><<<gg, 256>>>(key,   Wk, bk, pk);
    // V: linear path — single-chain accumulator
    gemm_v2<1, 0><<<gg, 256>>>(value, Wv, bv, pv);

    attn_v2<<<dim3(Sc / TQ, Bc * Hc), 512, SMEM_ATTN>>>(mask, topk);

    // output projection: linear path
    gemm_v2<0, 0><<<gg, 256>>>(pctx, Wo, bo, out);
}